// round 6
// baseline (speedup 1.0000x reference)
#include <cuda_runtime.h>

// DyDepthwiseConvAtten fused: dynamic 3-tap depthwise conv along C + LayerNorm.
// B*N = 102400 rows, C = 256. R5: TWO rows per warp iteration (ILP-2) —
// 8 front-batched LDG.128 (MLP 8) and interleaved shuffle-reduction chains so
// the 26-cyc SHFL latency of one row hides behind the other. Constants in
// conflict-free SMEM. Streaming cache hints (no reuse).

#define C_DIM  256
#define LN_EPS 1e-5f
#define FULL   0xFFFFFFFFu

__global__ __launch_bounds__(256, 4)
void dydwconv_ln_kernel(const float* __restrict__ q,
                        const float* __restrict__ v,
                        const float* __restrict__ Ww,     // [3,256]
                        const float* __restrict__ bw,     // [3]
                        const float* __restrict__ gamma,  // [256]
                        const float* __restrict__ beta,   // [256]
                        float* __restrict__ out,
                        int rows, int total_warps)
{
    // sW[k][i][lane] = const_k[channel = lane*8 + i]; addr = i*32+lane -> conflict-free
    __shared__ float sW[5][8][32];

    const int tid  = threadIdx.x;
    const int lane = tid & 31;
    {
        const int i  = tid >> 5;
        const int ch = lane * 8 + i;
        sW[0][i][lane] = Ww[ch];
        sW[1][i][lane] = Ww[C_DIM + ch];
        sW[2][i][lane] = Ww[2 * C_DIM + ch];
        sW[3][i][lane] = gamma[ch];
        sW[4][i][lane] = beta[ch];
    }
    __syncthreads();

    const float bw0 = bw[0], bw1 = bw[1], bw2 = bw[2];

    const int warp_g = (blockIdx.x * blockDim.x + tid) >> 5;
    const int cbase  = lane * 8;
    const int rstep  = 2 * total_warps;

    for (int r0 = 2 * warp_g; r0 < rows; r0 += rstep) {
        const size_t base0 = (size_t)r0 * C_DIM + cbase;
        const size_t base1 = base0 + C_DIM;          // row r0+1 (rows is even)

        // ---- 8 front-batched 128-bit streaming loads ----
        const float4 q0a = __ldcs((const float4*)(q + base0));
        const float4 q0b = __ldcs((const float4*)(q + base0) + 1);
        const float4 q1a = __ldcs((const float4*)(q + base1));
        const float4 q1b = __ldcs((const float4*)(q + base1) + 1);
        const float4 v0a = __ldcs((const float4*)(v + base0));
        const float4 v0b = __ldcs((const float4*)(v + base0) + 1);
        const float4 v1a = __ldcs((const float4*)(v + base1));
        const float4 v1b = __ldcs((const float4*)(v + base1) + 1);

        float Q0[8] = {q0a.x,q0a.y,q0a.z,q0a.w,q0b.x,q0b.y,q0b.z,q0b.w};
        float Q1[8] = {q1a.x,q1a.y,q1a.z,q1a.w,q1b.x,q1b.y,q1b.z,q1b.w};
        float V0[8] = {v0a.x,v0a.y,v0a.z,v0a.w,v0b.x,v0b.y,v0b.z,v0b.w};
        float V1[8] = {v1a.x,v1a.y,v1a.z,v1a.w,v1b.x,v1b.y,v1b.z,v1b.w};

        // ---- dynamic weights, both rows, 6 interleaved chains ----
        float a0 = 0.f, a1 = 0.f, a2 = 0.f;   // row 0
        float b0 = 0.f, b1 = 0.f, b2 = 0.f;   // row 1
        #pragma unroll
        for (int i = 0; i < 8; i++) {
            const float w0c = sW[0][i][lane];
            const float w1c = sW[1][i][lane];
            const float w2c = sW[2][i][lane];
            a0 = fmaf(Q0[i], w0c, a0);  b0 = fmaf(Q1[i], w0c, b0);
            a1 = fmaf(Q0[i], w1c, a1);  b1 = fmaf(Q1[i], w1c, b1);
            a2 = fmaf(Q0[i], w2c, a2);  b2 = fmaf(Q1[i], w2c, b2);
        }
        #pragma unroll
        for (int off = 16; off > 0; off >>= 1) {
            a0 += __shfl_xor_sync(FULL, a0, off);
            b0 += __shfl_xor_sync(FULL, b0, off);
            a1 += __shfl_xor_sync(FULL, a1, off);
            b1 += __shfl_xor_sync(FULL, b1, off);
            a2 += __shfl_xor_sync(FULL, a2, off);
            b2 += __shfl_xor_sync(FULL, b2, off);
        }
        const float w00 = bw0 + a0, w01 = bw1 + a1, w02 = bw2 + a2;
        const float w10 = bw0 + b0, w11 = bw1 + b1, w12 = bw2 + b2;

        // ---- halo exchange (zero padded) ----
        float vl0 = __shfl_up_sync(FULL, V0[7], 1);
        float vl1 = __shfl_up_sync(FULL, V1[7], 1);
        float vr0 = __shfl_down_sync(FULL, V0[0], 1);
        float vr1 = __shfl_down_sync(FULL, V1[0], 1);
        if (lane == 0)  { vl0 = 0.f; vl1 = 0.f; }
        if (lane == 31) { vr0 = 0.f; vr1 = 0.f; }

        // ---- 3-tap conv, in place (carry register), + LN partials ----
        float s0 = 0.f, ss0 = 0.f, s1 = 0.f, ss1 = 0.f;
        float c0 = vl0, c1 = vl1;                 // V[i-1]
        #pragma unroll
        for (int i = 0; i < 8; i++) {
            const float cur0 = V0[i], cur1 = V1[i];
            const float nx0 = (i < 7) ? V0[i + 1] : vr0;
            const float nx1 = (i < 7) ? V1[i + 1] : vr1;
            const float o0 = c0 * w00 + cur0 * w01 + nx0 * w02;
            const float o1 = c1 * w10 + cur1 * w11 + nx1 * w12;
            V0[i] = o0;  V1[i] = o1;
            s0 += o0;  ss0 = fmaf(o0, o0, ss0);
            s1 += o1;  ss1 = fmaf(o1, o1, ss1);
            c0 = cur0; c1 = cur1;
        }
        #pragma unroll
        for (int off = 16; off > 0; off >>= 1) {
            s0  += __shfl_xor_sync(FULL, s0,  off);
            s1  += __shfl_xor_sync(FULL, s1,  off);
            ss0 += __shfl_xor_sync(FULL, ss0, off);
            ss1 += __shfl_xor_sync(FULL, ss1, off);
        }
        const float m0   = s0  * (1.0f / C_DIM);
        const float m1   = s1  * (1.0f / C_DIM);
        const float inv0 = rsqrtf(ss0 * (1.0f / C_DIM) - m0 * m0 + LN_EPS);
        const float inv1 = rsqrtf(ss1 * (1.0f / C_DIM) - m1 * m1 + LN_EPS);

        // ---- normalize + affine + streaming stores ----
        float4 r0a, r0b, r1a, r1b;
        {
            float* p0 = &r0a.x; float* p1 = &r1a.x;
            #pragma unroll
            for (int i = 0; i < 4; i++) {
                const float g = sW[3][i][lane], bt = sW[4][i][lane];
                p0[i] = (V0[i] - m0) * inv0 * g + bt;
                p1[i] = (V1[i] - m1) * inv1 * g + bt;
            }
            float* p2 = &r0b.x; float* p3 = &r1b.x;
            #pragma unroll
            for (int i = 0; i < 4; i++) {
                const float g = sW[3][i + 4][lane], bt = sW[4][i + 4][lane];
                p2[i] = (V0[i + 4] - m0) * inv0 * g + bt;
                p3[i] = (V1[i + 4] - m1) * inv1 * g + bt;
            }
        }
        __stcs((float4*)(out + base0),     r0a);
        __stcs((float4*)(out + base0) + 1, r0b);
        __stcs((float4*)(out + base1),     r1a);
        __stcs((float4*)(out + base1) + 1, r1b);
    }
}

extern "C" void kernel_launch(void* const* d_in, const int* in_sizes, int n_in,
                              void* d_out, int out_size)
{
    const float* q     = (const float*)d_in[0];
    const float* v     = (const float*)d_in[1];
    const float* Ww    = (const float*)d_in[2];
    const float* bw    = (const float*)d_in[3];
    const float* gamma = (const float*)d_in[4];
    const float* beta  = (const float*)d_in[5];
    float* out = (float*)d_out;

    const int rows = in_sizes[0] / C_DIM;        // 102400
    const int grid = 640;                        // 5120 warps * 10 pairs = 102400 rows
    const int total_warps = grid * (256 / 32);   // 5120
    dydwconv_ln_kernel<<<grid, 256>>>(q, v, Ww, bw, gamma, beta, out,
                                      rows, total_warps);
}

// round 7
// speedup vs baseline: 1.0005x; 1.0005x over previous
#include <cuda_runtime.h>

// DyDepthwiseConvAtten fused: dynamic 3-tap depthwise conv along C + LayerNorm.
// B*N = 102400 rows, C = 256. R6: ILP-2 (two rows per warp iteration, 8
// front-batched LDG.128, interleaved shuffle chains) with L2-CACHEABLE loads
// (inter-replay L2 reuse of q/v -- 210MB inputs vs 126MB L2) and evict-first
// (__stcs) stores so the never-re-read output doesn't evict the inputs.

#define C_DIM  256
#define LN_EPS 1e-5f
#define FULL   0xFFFFFFFFu

__global__ __launch_bounds__(256, 4)
void dydwconv_ln_kernel(const float* __restrict__ q,
                        const float* __restrict__ v,
                        const float* __restrict__ Ww,     // [3,256]
                        const float* __restrict__ bw,     // [3]
                        const float* __restrict__ gamma,  // [256]
                        const float* __restrict__ beta,   // [256]
                        float* __restrict__ out,
                        int rows, int total_warps)
{
    // sW[k][i][lane] = const_k[channel = lane*8 + i]; addr = i*32+lane -> conflict-free
    __shared__ float sW[5][8][32];

    const int tid  = threadIdx.x;
    const int lane = tid & 31;
    {
        const int i  = tid >> 5;
        const int ch = lane * 8 + i;
        sW[0][i][lane] = Ww[ch];
        sW[1][i][lane] = Ww[C_DIM + ch];
        sW[2][i][lane] = Ww[2 * C_DIM + ch];
        sW[3][i][lane] = gamma[ch];
        sW[4][i][lane] = beta[ch];
    }
    __syncthreads();

    const float bw0 = bw[0], bw1 = bw[1], bw2 = bw[2];

    const int warp_g = (blockIdx.x * blockDim.x + tid) >> 5;
    const int cbase  = lane * 8;
    const int rstep  = 2 * total_warps;

    for (int r0 = 2 * warp_g; r0 < rows; r0 += rstep) {
        const size_t base0 = (size_t)r0 * C_DIM + cbase;
        const size_t base1 = base0 + C_DIM;          // row r0+1 (rows is even)

        // ---- 8 front-batched 128-bit loads (L2-cacheable: replay reuse) ----
        const float4 q0a = ((const float4*)(q + base0))[0];
        const float4 q0b = ((const float4*)(q + base0))[1];
        const float4 q1a = ((const float4*)(q + base1))[0];
        const float4 q1b = ((const float4*)(q + base1))[1];
        const float4 v0a = ((const float4*)(v + base0))[0];
        const float4 v0b = ((const float4*)(v + base0))[1];
        const float4 v1a = ((const float4*)(v + base1))[0];
        const float4 v1b = ((const float4*)(v + base1))[1];

        float Q0[8] = {q0a.x,q0a.y,q0a.z,q0a.w,q0b.x,q0b.y,q0b.z,q0b.w};
        float Q1[8] = {q1a.x,q1a.y,q1a.z,q1a.w,q1b.x,q1b.y,q1b.z,q1b.w};
        float V0[8] = {v0a.x,v0a.y,v0a.z,v0a.w,v0b.x,v0b.y,v0b.z,v0b.w};
        float V1[8] = {v1a.x,v1a.y,v1a.z,v1a.w,v1b.x,v1b.y,v1b.z,v1b.w};

        // ---- dynamic weights, both rows, 6 interleaved chains ----
        float a0 = 0.f, a1 = 0.f, a2 = 0.f;   // row 0
        float b0 = 0.f, b1 = 0.f, b2 = 0.f;   // row 1
        #pragma unroll
        for (int i = 0; i < 8; i++) {
            const float w0c = sW[0][i][lane];
            const float w1c = sW[1][i][lane];
            const float w2c = sW[2][i][lane];
            a0 = fmaf(Q0[i], w0c, a0);  b0 = fmaf(Q1[i], w0c, b0);
            a1 = fmaf(Q0[i], w1c, a1);  b1 = fmaf(Q1[i], w1c, b1);
            a2 = fmaf(Q0[i], w2c, a2);  b2 = fmaf(Q1[i], w2c, b2);
        }
        #pragma unroll
        for (int off = 16; off > 0; off >>= 1) {
            a0 += __shfl_xor_sync(FULL, a0, off);
            b0 += __shfl_xor_sync(FULL, b0, off);
            a1 += __shfl_xor_sync(FULL, a1, off);
            b1 += __shfl_xor_sync(FULL, b1, off);
            a2 += __shfl_xor_sync(FULL, a2, off);
            b2 += __shfl_xor_sync(FULL, b2, off);
        }
        const float w00 = bw0 + a0, w01 = bw1 + a1, w02 = bw2 + a2;
        const float w10 = bw0 + b0, w11 = bw1 + b1, w12 = bw2 + b2;

        // ---- halo exchange (zero padded) ----
        float vl0 = __shfl_up_sync(FULL, V0[7], 1);
        float vl1 = __shfl_up_sync(FULL, V1[7], 1);
        float vr0 = __shfl_down_sync(FULL, V0[0], 1);
        float vr1 = __shfl_down_sync(FULL, V1[0], 1);
        if (lane == 0)  { vl0 = 0.f; vl1 = 0.f; }
        if (lane == 31) { vr0 = 0.f; vr1 = 0.f; }

        // ---- 3-tap conv, in place (carry register), + LN partials ----
        float s0 = 0.f, ss0 = 0.f, s1 = 0.f, ss1 = 0.f;
        float c0 = vl0, c1 = vl1;                 // V[i-1]
        #pragma unroll
        for (int i = 0; i < 8; i++) {
            const float cur0 = V0[i], cur1 = V1[i];
            const float nx0 = (i < 7) ? V0[i + 1] : vr0;
            const float nx1 = (i < 7) ? V1[i + 1] : vr1;
            const float o0 = c0 * w00 + cur0 * w01 + nx0 * w02;
            const float o1 = c1 * w10 + cur1 * w11 + nx1 * w12;
            V0[i] = o0;  V1[i] = o1;
            s0 += o0;  ss0 = fmaf(o0, o0, ss0);
            s1 += o1;  ss1 = fmaf(o1, o1, ss1);
            c0 = cur0; c1 = cur1;
        }
        #pragma unroll
        for (int off = 16; off > 0; off >>= 1) {
            s0  += __shfl_xor_sync(FULL, s0,  off);
            s1  += __shfl_xor_sync(FULL, s1,  off);
            ss0 += __shfl_xor_sync(FULL, ss0, off);
            ss1 += __shfl_xor_sync(FULL, ss1, off);
        }
        const float m0   = s0  * (1.0f / C_DIM);
        const float m1   = s1  * (1.0f / C_DIM);
        const float inv0 = rsqrtf(ss0 * (1.0f / C_DIM) - m0 * m0 + LN_EPS);
        const float inv1 = rsqrtf(ss1 * (1.0f / C_DIM) - m1 * m1 + LN_EPS);

        // ---- normalize + affine + evict-first stores (output never re-read) ----
        float4 r0a, r0b, r1a, r1b;
        {
            float* p0 = &r0a.x; float* p1 = &r1a.x;
            #pragma unroll
            for (int i = 0; i < 4; i++) {
                const float g = sW[3][i][lane], bt = sW[4][i][lane];
                p0[i] = (V0[i] - m0) * inv0 * g + bt;
                p1[i] = (V1[i] - m1) * inv1 * g + bt;
            }
            float* p2 = &r0b.x; float* p3 = &r1b.x;
            #pragma unroll
            for (int i = 0; i < 4; i++) {
                const float g = sW[3][i + 4][lane], bt = sW[4][i + 4][lane];
                p2[i] = (V0[i + 4] - m0) * inv0 * g + bt;
                p3[i] = (V1[i + 4] - m1) * inv1 * g + bt;
            }
        }
        __stcs((float4*)(out + base0),     r0a);
        __stcs((float4*)(out + base0) + 1, r0b);
        __stcs((float4*)(out + base1),     r1a);
        __stcs((float4*)(out + base1) + 1, r1b);
    }
}

extern "C" void kernel_launch(void* const* d_in, const int* in_sizes, int n_in,
                              void* d_out, int out_size)
{
    const float* q     = (const float*)d_in[0];
    const float* v     = (const float*)d_in[1];
    const float* Ww    = (const float*)d_in[2];
    const float* bw    = (const float*)d_in[3];
    const float* gamma = (const float*)d_in[4];
    const float* beta  = (const float*)d_in[5];
    float* out = (float*)d_out;

    const int rows = in_sizes[0] / C_DIM;        // 102400
    const int grid = 640;                        // 5120 warps * 10 pairs = 102400 rows
    const int total_warps = grid * (256 / 32);   // 5120
    dydwconv_ln_kernel<<<grid, 256>>>(q, v, Ww, bw, gamma, beta, out,
                                      rows, total_warps);
}